// round 2
// baseline (speedup 1.0000x reference)
#include <cuda_runtime.h>
#include <cuda_bf16.h>

// Shapes fixed by the problem: x[2,2048,1024] f32, W[32,1024,1024] f32,
// b[32,1024] f32, ids[8] (int32 in practice: JAX x64 disabled downcasts the
// requested int64!), weights[8] f32. out[2,2048,1024] f32.
// Algebra: out = x @ (sum_k w_k W[ids_k])^T + sum_k w_k b[ids_k]
#define D_IN  1024
#define D_OUT 1024
#define N_ADAPT 32

// Scratch (no cudaMalloc allowed): mixed weight matrix + mixed bias.
__device__ float g_Wmix[D_OUT * D_IN];
__device__ float g_bmix[D_OUT];

// ---------------------------------------------------------------------------
// ids dtype detection: reads only the first K int32 words (in-bounds for both
// int32 and int64 buffers). Little-endian int64 values < 2^32 leave every odd
// int32 lane zero; int32 id data has ids at odd lanes.
// ---------------------------------------------------------------------------
__device__ __forceinline__ bool ids_look_i64(const void* idsptr, int K) {
    const int* p = (const int*)idsptr;
    bool odd_all_zero = true;
    for (int k = 1; k < K; k += 2)
        if (p[k] != 0) odd_all_zero = false;
    // even lanes must be valid ids in either interpretation
    bool even_valid = true;
    for (int k = 0; k < K; k += 2)
        if (p[k] < 0 || p[k] >= N_ADAPT) even_valid = false;
    return odd_all_zero && even_valid;
}

__device__ __forceinline__ int load_id(const void* idsptr, int k, bool is64) {
    if (is64) return (int)((const long long*)idsptr)[k];
    return ((const int*)idsptr)[k];
}

// ---------------------------------------------------------------------------
// Kernel 1: Wmix[o,d] = sum_k w_k * W[ids_k, o, d]   (vectorized float4)
// ---------------------------------------------------------------------------
__global__ void mix_w_kernel(const float* __restrict__ W,
                             const void* __restrict__ ids,
                             const float* __restrict__ wts, int K) {
    const int OD4 = D_OUT * D_IN / 4;
    int i = blockIdx.x * blockDim.x + threadIdx.x;
    if (i >= OD4) return;
    const bool is64 = ids_look_i64(ids, K);
    const float4* W4 = reinterpret_cast<const float4*>(W);
    float4 acc = make_float4(0.f, 0.f, 0.f, 0.f);
    for (int k = 0; k < K; k++) {
        float w = __ldg(&wts[k]);
        long long id = load_id(ids, k, is64);
        float4 v = __ldg(&W4[id * (long long)OD4 + i]);
        acc.x += w * v.x;
        acc.y += w * v.y;
        acc.z += w * v.z;
        acc.w += w * v.w;
    }
    reinterpret_cast<float4*>(g_Wmix)[i] = acc;
}

// ---------------------------------------------------------------------------
// Kernel 2: bmix[o] = sum_k w_k * b[ids_k, o]
// ---------------------------------------------------------------------------
__global__ void mix_b_kernel(const float* __restrict__ b,
                             const void* __restrict__ ids,
                             const float* __restrict__ wts, int K) {
    int i = blockIdx.x * blockDim.x + threadIdx.x;
    if (i >= D_OUT) return;
    const bool is64 = ids_look_i64(ids, K);
    float acc = 0.f;
    for (int k = 0; k < K; k++) {
        long long id = load_id(ids, k, is64);
        acc += __ldg(&wts[k]) * __ldg(&b[id * (long long)D_OUT + i]);
    }
    g_bmix[i] = acc;
}

// ---------------------------------------------------------------------------
// Kernel 3: C[m,o] = sum_d A[m,d] * Wmix[o,d] + bmix[o]
// Classic 128x128x8 register-blocked SGEMM, NT layout (both operands K-major).
// 256 threads; each thread computes an 8x8 microtile split as 2x2 of 4x4
// quadrants so float4 LDS reads are phase-conflict-free.
// ---------------------------------------------------------------------------
#define BM 128
#define BN 128
#define BK 8

__global__ void __launch_bounds__(256)
gemm_kernel(const float* __restrict__ A, float* __restrict__ C, int M) {
    __shared__ float As[BK][BM];
    __shared__ float Bs[BK][BN];

    const float* Bmat = g_Wmix;

    const int tid = threadIdx.x;
    const int bn = blockIdx.x;   // output-column tile
    const int bm = blockIdx.y;   // output-row tile

    // Global->shared staging: 2 threads per tile row, float4 each (128x8 tile)
    const int arow = tid >> 1;          // 0..127
    const int acol = (tid & 1) * 4;     // 0 or 4
    const float* Ag = A    + (size_t)(bm * BM + arow) * D_IN + acol;
    const float* Bg = Bmat + (size_t)(bn * BN + arow) * D_IN + acol;

    const int tx = tid & 15;
    const int ty = tid >> 4;
    const int col0 = tx * 4, col1 = 64 + tx * 4;
    const int row0 = ty * 4, row1 = 64 + ty * 4;

    float acc[8][8];
#pragma unroll
    for (int i = 0; i < 8; i++)
#pragma unroll
        for (int j = 0; j < 8; j++) acc[i][j] = 0.f;

    for (int k0 = 0; k0 < D_IN; k0 += BK) {
        float4 av = *reinterpret_cast<const float4*>(Ag + k0);
        float4 bv = *reinterpret_cast<const float4*>(Bg + k0);
        // store transposed: smem is [k][mn]
        As[acol + 0][arow] = av.x;
        As[acol + 1][arow] = av.y;
        As[acol + 2][arow] = av.z;
        As[acol + 3][arow] = av.w;
        Bs[acol + 0][arow] = bv.x;
        Bs[acol + 1][arow] = bv.y;
        Bs[acol + 2][arow] = bv.z;
        Bs[acol + 3][arow] = bv.w;
        __syncthreads();

#pragma unroll
        for (int k = 0; k < BK; k++) {
            float4 a0 = *reinterpret_cast<const float4*>(&As[k][row0]);
            float4 a1 = *reinterpret_cast<const float4*>(&As[k][row1]);
            float4 b0 = *reinterpret_cast<const float4*>(&Bs[k][col0]);
            float4 b1 = *reinterpret_cast<const float4*>(&Bs[k][col1]);
            float a[8] = {a0.x, a0.y, a0.z, a0.w, a1.x, a1.y, a1.z, a1.w};
            float bb[8] = {b0.x, b0.y, b0.z, b0.w, b1.x, b1.y, b1.z, b1.w};
#pragma unroll
            for (int i = 0; i < 8; i++)
#pragma unroll
                for (int j = 0; j < 8; j++)
                    acc[i][j] += a[i] * bb[j];
        }
        __syncthreads();
    }

    // Epilogue: add bias, vectorized stores.
    float4 bias0 = *reinterpret_cast<const float4*>(&g_bmix[bn * BN + col0]);
    float4 bias1 = *reinterpret_cast<const float4*>(&g_bmix[bn * BN + col1]);
    float biasv[8] = {bias0.x, bias0.y, bias0.z, bias0.w,
                      bias1.x, bias1.y, bias1.z, bias1.w};

#pragma unroll
    for (int i = 0; i < 8; i++) {
        int row = bm * BM + (i < 4 ? row0 + i : row1 + (i - 4));
        float4 o0, o1;
        o0.x = acc[i][0] + biasv[0];
        o0.y = acc[i][1] + biasv[1];
        o0.z = acc[i][2] + biasv[2];
        o0.w = acc[i][3] + biasv[3];
        o1.x = acc[i][4] + biasv[4];
        o1.y = acc[i][5] + biasv[5];
        o1.z = acc[i][6] + biasv[6];
        o1.w = acc[i][7] + biasv[7];
        *reinterpret_cast<float4*>(&C[(size_t)row * D_OUT + bn * BN + col0]) = o0;
        *reinterpret_cast<float4*>(&C[(size_t)row * D_OUT + bn * BN + col1]) = o1;
    }
}

// ---------------------------------------------------------------------------
extern "C" void kernel_launch(void* const* d_in, const int* in_sizes, int n_in,
                              void* d_out, int out_size) {
    const float* x   = (const float*)d_in[0];   // [B,S,D_IN]
    const float* W   = (const float*)d_in[1];   // [N,D_OUT,D_IN]
    const float* b   = (const float*)d_in[2];   // [N,D_OUT]
    const void*  ids = d_in[3];                 // [K] int32 or int64
    const float* wts = (const float*)d_in[4];   // [K]

    const int K = in_sizes[3];
    const int M = in_sizes[0] / D_IN;   // B*S = 4096

    // 1) mix weights into g_Wmix
    {
        const int OD4 = D_OUT * D_IN / 4;
        mix_w_kernel<<<(OD4 + 255) / 256, 256>>>(W, ids, wts, K);
    }
    // 2) mix bias
    mix_b_kernel<<<(D_OUT + 255) / 256, 256>>>(b, ids, wts, K);
    // 3) single fused GEMM + bias epilogue
    {
        dim3 grid(D_OUT / BN, M / BM);
        gemm_kernel<<<grid, 256>>>(x, (float*)d_out, M);
    }
}

// round 4
// speedup vs baseline: 2.2802x; 2.2802x over previous
#include <cuda_runtime.h>
#include <cuda_bf16.h>
#include <cstdint>

// out = x @ (sum_k w_k W[ids_k])^T + sum_k w_k b[ids_k]
// x[4096,1024] f32, W[32,1024,1024] f32, b[32,1024] f32, ids[8], weights[8].
// GEMM on mma.sync bf16 (compute_103-safe; tcgen05 'a'-features unavailable
// in this build) with hi/lo error-compensated split, 3 passes, fp32 accum.
#define D_IN    1024
#define D_OUT   1024
#define M_TOTAL 4096
#define N_ADAPT 32

// -------- scratch (__device__ globals; no cudaMalloc allowed) ---------------
__device__ __nv_bfloat16 g_XHi[M_TOTAL * D_IN];
__device__ __nv_bfloat16 g_XLo[M_TOTAL * D_IN];
__device__ __nv_bfloat16 g_WHi[D_OUT * D_IN];
__device__ __nv_bfloat16 g_WLo[D_OUT * D_IN];
__device__ float         g_bmix[D_OUT];

// -------- PTX helpers (all sm_80-era, valid for compute_103) ----------------
__device__ __forceinline__ uint32_t smem_u32(const void* p) {
    uint32_t a;
    asm("{ .reg .u64 t; cvta.to.shared.u64 t, %1; cvt.u32.u64 %0, t; }"
        : "=r"(a) : "l"(p));
    return a;
}
__device__ __forceinline__ void cp_async16(uint32_t dst, const void* src) {
    asm volatile("cp.async.cg.shared.global [%0], [%1], 16;"
                 :: "r"(dst), "l"(src) : "memory");
}
__device__ __forceinline__ void cp_commit() {
    asm volatile("cp.async.commit_group;" ::: "memory");
}
template <int N> __device__ __forceinline__ void cp_wait() {
    asm volatile("cp.async.wait_group %0;" :: "n"(N) : "memory");
}
__device__ __forceinline__ void ldsm_x4(uint32_t& r0, uint32_t& r1,
                                        uint32_t& r2, uint32_t& r3, uint32_t a) {
    asm volatile("ldmatrix.sync.aligned.m8n8.x4.shared.b16 {%0,%1,%2,%3}, [%4];"
                 : "=r"(r0), "=r"(r1), "=r"(r2), "=r"(r3) : "r"(a));
}
__device__ __forceinline__ void mma_bf16(float* c, const uint32_t* a,
                                         const uint32_t* b) {
    asm volatile(
        "mma.sync.aligned.m16n8k16.row.col.f32.bf16.bf16.f32 "
        "{%0,%1,%2,%3}, {%4,%5,%6,%7}, {%8,%9}, {%0,%1,%2,%3};"
        : "+f"(c[0]), "+f"(c[1]), "+f"(c[2]), "+f"(c[3])
        : "r"(a[0]), "r"(a[1]), "r"(a[2]), "r"(a[3]), "r"(b[0]), "r"(b[1]));
}

// -------- ids dtype detection (JAX x64-off downcasts int64 -> int32) --------
__device__ __forceinline__ bool ids_look_i64(const void* idsptr, int K) {
    const int* p = (const int*)idsptr;
    bool odd_zero = true, even_valid = true;
    for (int k = 1; k < K; k += 2) if (p[k] != 0) odd_zero = false;
    for (int k = 0; k < K; k += 2) if (p[k] < 0 || p[k] >= N_ADAPT) even_valid = false;
    return odd_zero && even_valid;
}
__device__ __forceinline__ int load_id(const void* idsptr, int k, bool is64) {
    return is64 ? (int)((const long long*)idsptr)[k] : ((const int*)idsptr)[k];
}

// -------- hi/lo split --------------------------------------------------------
__device__ __forceinline__ void split_bf16(float v, unsigned short& h, unsigned short& l) {
    __nv_bfloat16 hi = __float2bfloat16_rn(v);
    __nv_bfloat16 lo = __float2bfloat16_rn(v - __bfloat162float(hi));
    h = __bfloat16_as_ushort(hi);
    l = __bfloat16_as_ushort(lo);
}

// ---------------------------------------------------------------------------
// Kernel 1: x (f32) -> XHi/XLo (bf16 split)
// ---------------------------------------------------------------------------
__global__ void prep_x_kernel(const float* __restrict__ x) {
    int i = blockIdx.x * blockDim.x + threadIdx.x;  // float4 index
    float4 v = __ldg(&((const float4*)x)[i]);
    unsigned short h0, h1, h2, h3, l0, l1, l2, l3;
    split_bf16(v.x, h0, l0); split_bf16(v.y, h1, l1);
    split_bf16(v.z, h2, l2); split_bf16(v.w, h3, l3);
    ((uint2*)g_XHi)[i] = make_uint2((uint32_t)h0 | ((uint32_t)h1 << 16),
                                    (uint32_t)h2 | ((uint32_t)h3 << 16));
    ((uint2*)g_XLo)[i] = make_uint2((uint32_t)l0 | ((uint32_t)l1 << 16),
                                    (uint32_t)l2 | ((uint32_t)l3 << 16));
}

// ---------------------------------------------------------------------------
// Kernel 2: Wmix = sum_k w_k W[ids_k] -> WHi/WLo bf16 split
// ---------------------------------------------------------------------------
__global__ void mix_w_kernel(const float* __restrict__ W,
                             const void* __restrict__ ids,
                             const float* __restrict__ wts, int K) {
    const int OD4 = D_OUT * D_IN / 4;
    int i = blockIdx.x * blockDim.x + threadIdx.x;
    if (i >= OD4) return;
    const bool is64 = ids_look_i64(ids, K);
    const float4* W4 = (const float4*)W;
    float4 acc = make_float4(0.f, 0.f, 0.f, 0.f);
    for (int k = 0; k < K; k++) {
        float w = __ldg(&wts[k]);
        long long id = load_id(ids, k, is64);
        float4 v = __ldg(&W4[id * (long long)OD4 + i]);
        acc.x += w * v.x; acc.y += w * v.y; acc.z += w * v.z; acc.w += w * v.w;
    }
    unsigned short h0, h1, h2, h3, l0, l1, l2, l3;
    split_bf16(acc.x, h0, l0); split_bf16(acc.y, h1, l1);
    split_bf16(acc.z, h2, l2); split_bf16(acc.w, h3, l3);
    ((uint2*)g_WHi)[i] = make_uint2((uint32_t)h0 | ((uint32_t)h1 << 16),
                                    (uint32_t)h2 | ((uint32_t)h3 << 16));
    ((uint2*)g_WLo)[i] = make_uint2((uint32_t)l0 | ((uint32_t)l1 << 16),
                                    (uint32_t)l2 | ((uint32_t)l3 << 16));
}

// ---------------------------------------------------------------------------
// Kernel 3: bmix
// ---------------------------------------------------------------------------
__global__ void mix_b_kernel(const float* __restrict__ b,
                             const void* __restrict__ ids,
                             const float* __restrict__ wts, int K) {
    int i = blockIdx.x * blockDim.x + threadIdx.x;
    if (i >= D_OUT) return;
    const bool is64 = ids_look_i64(ids, K);
    float acc = 0.f;
    for (int k = 0; k < K; k++) {
        long long id = load_id(ids, k, is64);
        acc += __ldg(&wts[k]) * __ldg(&b[id * (long long)D_OUT + i]);
    }
    g_bmix[i] = acc;
}

// ---------------------------------------------------------------------------
// Kernel 4: mma.sync bf16 GEMM.  C[m,n] = sum_d x[m,d] Wmix[n,d] + bmix[n]
// CTA tile 128x128, K-chunk 32, 8 warps (2x4), warp tile 64x32.
// SMEM rows padded to 40 bf16 (80B) -> conflict-free ldmatrix.
// cp.async double buffering; 3 passes hi*hi + hi*lo + lo*hi.
// ---------------------------------------------------------------------------
#define MTILE 128
#define NTILE 128
#define KC    32
#define NCH   (D_IN / KC)        // 32 chunks
#define RSTR  40                 // padded row stride in bf16
// per-stage offsets (bf16 units): AHI, ALO, BHI, BLO each 128*40 = 5120
#define AHI 0
#define ALO 5120
#define BHI 10240
#define BLO 15360
#define STAGE_ELEMS 20480
#define SMEM_BYTES  (2 * STAGE_ELEMS * 2)

__global__ void __launch_bounds__(256)
gemm_mma_kernel(float* __restrict__ C) {
    extern __shared__ __nv_bfloat16 sm[];
    const uint32_t sbase = smem_u32(sm);

    const int tid   = threadIdx.x;
    const int lane  = tid & 31;
    const int wid   = tid >> 5;
    const int warp_m = wid & 1;        // 2 warps in M (64 rows each)
    const int warp_n = wid >> 1;       // 4 warps in N (32 cols each)
    const int m0 = blockIdx.y * MTILE;
    const int n0 = blockIdx.x * NTILE;

    // ---- global->smem load assignment: each thread: row = tid>>1 (0..127),
    // two 16B chunks (kc = (tid&1)*2, +1) for each of the 4 arrays.
    const int lrow = tid >> 1;
    const int lkc  = (tid & 1) * 2;
    const __nv_bfloat16* gAH = g_XHi + (size_t)(m0 + lrow) * D_IN + lkc * 8;
    const __nv_bfloat16* gAL = g_XLo + (size_t)(m0 + lrow) * D_IN + lkc * 8;
    const __nv_bfloat16* gBH = g_WHi + (size_t)(n0 + lrow) * D_IN + lkc * 8;
    const __nv_bfloat16* gBL = g_WLo + (size_t)(n0 + lrow) * D_IN + lkc * 8;
    const uint32_t drow = (uint32_t)(lrow * RSTR + lkc * 8) * 2;  // byte off in stage

    auto load_stage = [&](int c, int stg) {
        const uint32_t sb = sbase + (uint32_t)stg * STAGE_ELEMS * 2;
        const size_t go = (size_t)c * KC;
#pragma unroll
        for (int j = 0; j < 2; j++) {
            const uint32_t d = drow + j * 16;
            cp_async16(sb + AHI * 2 + d, gAH + go + j * 8);
            cp_async16(sb + ALO * 2 + d, gAL + go + j * 8);
            cp_async16(sb + BHI * 2 + d, gBH + go + j * 8);
            cp_async16(sb + BLO * 2 + d, gBL + go + j * 8);
        }
        cp_commit();
    };

    // ---- ldmatrix per-thread source rows/cols (within tile) ----
    // A: lanes 0-15 -> rows (lane&15) @k0 ; lanes 16-31 -> same rows @k0+8
    const int a_row = (lane & 15);
    const int a_kof = (lane >> 4) * 8;
    // B: row = (lane>>4)*8 + (lane&7), kcol = ((lane>>3)&1)*8
    const int b_row = ((lane >> 4) << 3) + (lane & 7);
    const int b_kof = ((lane >> 3) & 1) * 8;

    float acc[4][4][4];
#pragma unroll
    for (int i = 0; i < 4; i++)
#pragma unroll
        for (int j = 0; j < 4; j++)
#pragma unroll
            for (int q = 0; q < 4; q++) acc[i][j][q] = 0.f;

    load_stage(0, 0);

    for (int c = 0; c < NCH; c++) {
        if (c + 1 < NCH) load_stage(c + 1, (c + 1) & 1);
        if (c + 1 < NCH) cp_wait<1>(); else cp_wait<0>();
        __syncthreads();

        const uint32_t sb = sbase + (uint32_t)(c & 1) * STAGE_ELEMS * 2;
#pragma unroll
        for (int ks = 0; ks < 2; ks++) {
            const int k0 = ks * 16;
            uint32_t ah[4][4], al[4][4];
#pragma unroll
            for (int mf = 0; mf < 4; mf++) {
                const uint32_t ro =
                    (uint32_t)((warp_m * 64 + mf * 16 + a_row) * RSTR + k0 + a_kof) * 2;
                ldsm_x4(ah[mf][0], ah[mf][1], ah[mf][2], ah[mf][3], sb + AHI * 2 + ro);
                ldsm_x4(al[mf][0], al[mf][1], al[mf][2], al[mf][3], sb + ALO * 2 + ro);
            }
            uint32_t bh[4][2], bl[4][2];
#pragma unroll
            for (int ng = 0; ng < 2; ng++) {
                const uint32_t ro =
                    (uint32_t)((warp_n * 32 + ng * 16 + b_row) * RSTR + k0 + b_kof) * 2;
                uint32_t r0, r1, r2, r3;
                ldsm_x4(r0, r1, r2, r3, sb + BHI * 2 + ro);
                bh[ng * 2][0] = r0; bh[ng * 2][1] = r1;
                bh[ng * 2 + 1][0] = r2; bh[ng * 2 + 1][1] = r3;
                ldsm_x4(r0, r1, r2, r3, sb + BLO * 2 + ro);
                bl[ng * 2][0] = r0; bl[ng * 2][1] = r1;
                bl[ng * 2 + 1][0] = r2; bl[ng * 2 + 1][1] = r3;
            }
#pragma unroll
            for (int mf = 0; mf < 4; mf++)
#pragma unroll
                for (int nf = 0; nf < 4; nf++) {
                    mma_bf16(acc[mf][nf], ah[mf], bh[nf]);
                    mma_bf16(acc[mf][nf], ah[mf], bl[nf]);
                    mma_bf16(acc[mf][nf], al[mf], bh[nf]);
                }
        }
        __syncthreads();
    }

    // ---- epilogue: add bias, store float2 pairs ----
    const int g = lane >> 2;            // 0..7
    const int cpair = (lane & 3) * 2;   // 0,2,4,6
#pragma unroll
    for (int mf = 0; mf < 4; mf++) {
        const int row = m0 + warp_m * 64 + mf * 16 + g;
#pragma unroll
        for (int nf = 0; nf < 4; nf++) {
            const int col = n0 + warp_n * 32 + nf * 8 + cpair;
            const float b0 = __ldg(&g_bmix[col]);
            const float b1 = __ldg(&g_bmix[col + 1]);
            float2 v0 = make_float2(acc[mf][nf][0] + b0, acc[mf][nf][1] + b1);
            float2 v1 = make_float2(acc[mf][nf][2] + b0, acc[mf][nf][3] + b1);
            *(float2*)(C + (size_t)row * D_OUT + col) = v0;
            *(float2*)(C + (size_t)(row + 8) * D_OUT + col) = v1;
        }
    }
}

// ---------------------------------------------------------------------------
extern "C" void kernel_launch(void* const* d_in, const int* in_sizes, int n_in,
                              void* d_out, int out_size) {
    const float* x   = (const float*)d_in[0];
    const float* W   = (const float*)d_in[1];
    const float* b   = (const float*)d_in[2];
    const void*  ids = d_in[3];
    const float* wts = (const float*)d_in[4];
    const int K = in_sizes[3];

    cudaFuncSetAttribute(gemm_mma_kernel,
                         cudaFuncAttributeMaxDynamicSharedMemorySize, SMEM_BYTES);

    prep_x_kernel<<<M_TOTAL * D_IN / 4 / 256, 256>>>(x);
    mix_w_kernel<<<D_OUT * D_IN / 4 / 256, 256>>>(W, ids, wts, K);
    mix_b_kernel<<<D_OUT / 256, 256>>>(b, ids, wts, K);

    dim3 grid(D_OUT / NTILE, M_TOTAL / MTILE);  // (8, 32) = 256 CTAs
    gemm_mma_kernel<<<grid, 256, SMEM_BYTES>>>((float*)d_out);
}

// round 5
// speedup vs baseline: 3.5714x; 1.5663x over previous
#include <cuda_runtime.h>
#include <cuda_fp16.h>
#include <cstdint>

// out = x @ (sum_k w_k W[ids_k])^T + sum_k w_k b[ids_k]
// fp16 2-pass scheme: x -> fp16 (err 2^-11), Wmix -> fp16 hi+lo (err 2^-22).
// acc = x*Wh + x*Wl in fp32. Predicted rel_err ~3e-4 < 1e-3.
#define D_IN    1024
#define D_OUT   1024
#define M_TOTAL 4096
#define N_ADAPT 32

__device__ __half g_Xf[M_TOTAL * D_IN];
__device__ __half g_WHi[D_OUT * D_IN];
__device__ __half g_WLo[D_OUT * D_IN];
__device__ float  g_bmix[D_OUT];

// -------- PTX helpers (sm_80-era, valid for compute_103) --------------------
__device__ __forceinline__ uint32_t smem_u32(const void* p) {
    uint32_t a;
    asm("{ .reg .u64 t; cvta.to.shared.u64 t, %1; cvt.u32.u64 %0, t; }"
        : "=r"(a) : "l"(p));
    return a;
}
__device__ __forceinline__ void cp_async16(uint32_t dst, const void* src) {
    asm volatile("cp.async.cg.shared.global [%0], [%1], 16;"
                 :: "r"(dst), "l"(src) : "memory");
}
__device__ __forceinline__ void cp_commit() {
    asm volatile("cp.async.commit_group;" ::: "memory");
}
template <int N> __device__ __forceinline__ void cp_wait() {
    asm volatile("cp.async.wait_group %0;" :: "n"(N) : "memory");
}
__device__ __forceinline__ void ldsm_x4(uint32_t& r0, uint32_t& r1,
                                        uint32_t& r2, uint32_t& r3, uint32_t a) {
    asm volatile("ldmatrix.sync.aligned.m8n8.x4.shared.b16 {%0,%1,%2,%3}, [%4];"
                 : "=r"(r0), "=r"(r1), "=r"(r2), "=r"(r3) : "r"(a));
}
__device__ __forceinline__ void mma_f16(float* c, const uint32_t* a,
                                        const uint32_t* b) {
    asm volatile(
        "mma.sync.aligned.m16n8k16.row.col.f32.f16.f16.f32 "
        "{%0,%1,%2,%3}, {%4,%5,%6,%7}, {%8,%9}, {%0,%1,%2,%3};"
        : "+f"(c[0]), "+f"(c[1]), "+f"(c[2]), "+f"(c[3])
        : "r"(a[0]), "r"(a[1]), "r"(a[2]), "r"(a[3]), "r"(b[0]), "r"(b[1]));
}

// -------- ids dtype detection (JAX x64-off downcasts int64 -> int32) --------
__device__ __forceinline__ bool ids_look_i64(const void* idsptr, int K) {
    const int* p = (const int*)idsptr;
    bool odd_zero = true, even_valid = true;
    for (int k = 1; k < K; k += 2) if (p[k] != 0) odd_zero = false;
    for (int k = 0; k < K; k += 2) if (p[k] < 0 || p[k] >= N_ADAPT) even_valid = false;
    return odd_zero && even_valid;
}
__device__ __forceinline__ int load_id(const void* idsptr, int k, bool is64) {
    return is64 ? (int)((const long long*)idsptr)[k] : ((const int*)idsptr)[k];
}

__device__ __forceinline__ void split_f16(float v, unsigned short& h, unsigned short& l) {
    __half hi = __float2half_rn(v);
    __half lo = __float2half_rn(v - __half2float(hi));
    h = __half_as_ushort(hi);
    l = __half_as_ushort(lo);
}

// ---------------------------------------------------------------------------
// Fused prep: blocks [0,4096): x->fp16 ; [4096,5120): Wmix->hi/lo ; 5120: bias
// ---------------------------------------------------------------------------
#define XBLKS 4096
#define WBLKS 1024
__global__ void prep_all_kernel(const float* __restrict__ x,
                                const float* __restrict__ W,
                                const float* __restrict__ b,
                                const void* __restrict__ ids,
                                const float* __restrict__ wts, int K) {
    const int bid = blockIdx.x;
    if (bid < XBLKS) {
        const int i = bid * 256 + threadIdx.x;   // float4 index into x
        float4 v = __ldg(&((const float4*)x)[i]);
        __half2 p0 = make_half2(__float2half_rn(v.x), __float2half_rn(v.y));
        __half2 p1 = make_half2(__float2half_rn(v.z), __float2half_rn(v.w));
        ((__half2*)g_Xf)[i * 2]     = p0;
        ((__half2*)g_Xf)[i * 2 + 1] = p1;
    } else if (bid < XBLKS + WBLKS) {
        const bool is64 = ids_look_i64(ids, K);
        const int i = (bid - XBLKS) * 256 + threadIdx.x;  // float4 index into Wmix
        const int OD4 = D_OUT * D_IN / 4;
        const float4* W4 = (const float4*)W;
        float4 acc = make_float4(0.f, 0.f, 0.f, 0.f);
        for (int k = 0; k < K; k++) {
            float w = __ldg(&wts[k]);
            long long id = load_id(ids, k, is64);
            float4 v = __ldg(&W4[id * (long long)OD4 + i]);
            acc.x += w * v.x; acc.y += w * v.y; acc.z += w * v.z; acc.w += w * v.w;
        }
        unsigned short h0, h1, h2, h3, l0, l1, l2, l3;
        split_f16(acc.x, h0, l0); split_f16(acc.y, h1, l1);
        split_f16(acc.z, h2, l2); split_f16(acc.w, h3, l3);
        ((uint2*)g_WHi)[i] = make_uint2((uint32_t)h0 | ((uint32_t)h1 << 16),
                                        (uint32_t)h2 | ((uint32_t)h3 << 16));
        ((uint2*)g_WLo)[i] = make_uint2((uint32_t)l0 | ((uint32_t)l1 << 16),
                                        (uint32_t)l2 | ((uint32_t)l3 << 16));
    } else {
        const bool is64 = ids_look_i64(ids, K);
        for (int i = threadIdx.x; i < D_OUT; i += 256) {
            float acc = 0.f;
            for (int k = 0; k < K; k++) {
                long long id = load_id(ids, k, is64);
                acc += __ldg(&wts[k]) * __ldg(&b[id * (long long)D_OUT + i]);
            }
            g_bmix[i] = acc;
        }
    }
}

// ---------------------------------------------------------------------------
// GEMM: C[m,n] = sum_d x[m,d] Wmix[n,d] + bmix[n]
// CTA tile 128x128, K-chunk 32, 8 warps (2 in M x 4 in N), warp tile 64x32.
// 3-stage cp.async pipeline, one __syncthreads per chunk.
// 2 MMA passes: x*Wh + x*Wl, fp32 accum.
// ---------------------------------------------------------------------------
#define MTILE 128
#define NTILE 128
#define KC    32
#define NCH   (D_IN / KC)          // 32
#define RSTR  40                   // padded row stride (halves): 80B rows
#define XOFF  0
#define WHOFF (128 * RSTR)
#define WLOFF (2 * 128 * RSTR)
#define STAGE_ELEMS (3 * 128 * RSTR)   // 15360 halves = 30720 B
#define NSTAGE 3
#define SMEM_BYTES (NSTAGE * STAGE_ELEMS * 2)   // 92160 B

__global__ void __launch_bounds__(256, 2)
gemm_mma_kernel(float* __restrict__ C) {
    extern __shared__ __half sm[];
    const uint32_t sbase = smem_u32(sm);

    const int tid    = threadIdx.x;
    const int lane   = tid & 31;
    const int wid    = tid >> 5;
    const int warp_m = wid & 1;
    const int warp_n = wid >> 1;
    const int m0 = blockIdx.y * MTILE;
    const int n0 = blockIdx.x * NTILE;

    // global->smem: row = tid>>1 (0..127); half of a 64B row per thread.
    const int lrow = tid >> 1;
    const int lkh  = (tid & 1) * 16;          // half-offset within 32-half row
    const __half* gX = g_Xf  + (size_t)(m0 + lrow) * D_IN + lkh;
    const __half* gH = g_WHi + (size_t)(n0 + lrow) * D_IN + lkh;
    const __half* gL = g_WLo + (size_t)(n0 + lrow) * D_IN + lkh;
    const uint32_t dst = (uint32_t)(lrow * RSTR + lkh) * 2;  // stage byte offset

    auto load_stage = [&](int c) {
        const uint32_t sb = sbase + (uint32_t)(c % NSTAGE) * STAGE_ELEMS * 2;
        const size_t go = (size_t)c * KC;
#pragma unroll
        for (int j = 0; j < 2; j++) {
            const uint32_t d = dst + j * 16;
            cp_async16(sb + XOFF  * 2 + d, gX + go + j * 8);
            cp_async16(sb + WHOFF * 2 + d, gH + go + j * 8);
            cp_async16(sb + WLOFF * 2 + d, gL + go + j * 8);
        }
    };

    // ldmatrix lane mapping (same as validated R4 layout)
    const int a_row = (lane & 15);
    const int a_kof = (lane >> 4) * 8;
    const int b_row = ((lane >> 4) << 3) + (lane & 7);
    const int b_kof = ((lane >> 3) & 1) * 8;

    float acc[4][4][4];
#pragma unroll
    for (int i = 0; i < 4; i++)
#pragma unroll
        for (int j = 0; j < 4; j++)
#pragma unroll
            for (int q = 0; q < 4; q++) acc[i][j][q] = 0.f;

    // prologue: stages 0,1 in flight
    load_stage(0); cp_commit();
    load_stage(1); cp_commit();

    for (int c = 0; c < NCH; c++) {
        cp_wait<NSTAGE - 2>();     // stage c resident
        __syncthreads();

        const uint32_t sb = sbase + (uint32_t)(c % NSTAGE) * STAGE_ELEMS * 2;
#pragma unroll
        for (int ks = 0; ks < 2; ks++) {
            const int k0 = ks * 16;
            uint32_t af[4][4];
#pragma unroll
            for (int mf = 0; mf < 4; mf++) {
                const uint32_t ro =
                    (uint32_t)((warp_m * 64 + mf * 16 + a_row) * RSTR + k0 + a_kof) * 2;
                ldsm_x4(af[mf][0], af[mf][1], af[mf][2], af[mf][3], sb + XOFF * 2 + ro);
            }
            uint32_t bh[4][2], bl[4][2];
#pragma unroll
            for (int ng = 0; ng < 2; ng++) {
                const uint32_t ro =
                    (uint32_t)((warp_n * 32 + ng * 16 + b_row) * RSTR + k0 + b_kof) * 2;
                uint32_t r0, r1, r2, r3;
                ldsm_x4(r0, r1, r2, r3, sb + WHOFF * 2 + ro);
                bh[ng * 2][0] = r0; bh[ng * 2][1] = r1;
                bh[ng * 2 + 1][0] = r2; bh[ng * 2 + 1][1] = r3;
                ldsm_x4(r0, r1, r2, r3, sb + WLOFF * 2 + ro);
                bl[ng * 2][0] = r0; bl[ng * 2][1] = r1;
                bl[ng * 2 + 1][0] = r2; bl[ng * 2 + 1][1] = r3;
            }
#pragma unroll
            for (int mf = 0; mf < 4; mf++)
#pragma unroll
                for (int nf = 0; nf < 4; nf++) {
                    mma_f16(acc[mf][nf], af[mf], bh[nf]);
                    mma_f16(acc[mf][nf], af[mf], bl[nf]);
                }
        }

        // issue next stage into the slot computed LAST iter (safe: all warps
        // passed this iter's __syncthreads => finished compute(c-1)).
        if (c + NSTAGE - 1 < NCH) load_stage(c + NSTAGE - 1);
        cp_commit();   // unconditional (empty groups at tail keep wait<> sound)
    }

    // epilogue: add bias, store float2 pairs
    const int g = lane >> 2;
    const int cpair = (lane & 3) * 2;
#pragma unroll
    for (int mf = 0; mf < 4; mf++) {
        const int row = m0 + warp_m * 64 + mf * 16 + g;
#pragma unroll
        for (int nf = 0; nf < 4; nf++) {
            const int col = n0 + warp_n * 32 + nf * 8 + cpair;
            const float b0 = __ldg(&g_bmix[col]);
            const float b1 = __ldg(&g_bmix[col + 1]);
            float2 v0 = make_float2(acc[mf][nf][0] + b0, acc[mf][nf][1] + b1);
            float2 v1 = make_float2(acc[mf][nf][2] + b0, acc[mf][nf][3] + b1);
            *(float2*)(C + (size_t)row * D_OUT + col) = v0;
            *(float2*)(C + (size_t)(row + 8) * D_OUT + col) = v1;
        }
    }
}

// ---------------------------------------------------------------------------
extern "C" void kernel_launch(void* const* d_in, const int* in_sizes, int n_in,
                              void* d_out, int out_size) {
    const float* x   = (const float*)d_in[0];
    const float* W   = (const float*)d_in[1];
    const float* b   = (const float*)d_in[2];
    const void*  ids = d_in[3];
    const float* wts = (const float*)d_in[4];
    const int K = in_sizes[3];

    cudaFuncSetAttribute(gemm_mma_kernel,
                         cudaFuncAttributeMaxDynamicSharedMemorySize, SMEM_BYTES);

    prep_all_kernel<<<XBLKS + WBLKS + 1, 256>>>(x, W, b, ids, wts, K);

    dim3 grid(D_OUT / NTILE, M_TOTAL / MTILE);  // (8, 32) = 256 CTAs
    gemm_mma_kernel<<<grid, 256, SMEM_BYTES>>>((float*)d_out);
}

// round 6
// speedup vs baseline: 4.7214x; 1.3220x over previous
#include <cuda_runtime.h>
#include <cuda_fp16.h>
#include <cstdint>

// out = x @ (sum_k w_k W[ids_k])^T + sum_k w_k b[ids_k]
// SINGLE-PASS fp16: x->fp16 (2^-11), Wmix->fp16 (2^-11); fp32 HMMA accum.
// Validated error model (R5 measured 2.08e-4 from x alone) predicts ~2.9e-4.
#define D_IN    1024
#define D_OUT   1024
#define M_TOTAL 4096
#define N_ADAPT 32

__device__ __half g_Xf[M_TOTAL * D_IN];
__device__ __half g_Wf[D_OUT * D_IN];
__device__ float  g_bmix[D_OUT];

// -------- PTX helpers (sm_80-era, valid for compute_103) --------------------
__device__ __forceinline__ uint32_t smem_u32(const void* p) {
    uint32_t a;
    asm("{ .reg .u64 t; cvta.to.shared.u64 t, %1; cvt.u32.u64 %0, t; }"
        : "=r"(a) : "l"(p));
    return a;
}
__device__ __forceinline__ void cp_async16(uint32_t dst, const void* src) {
    asm volatile("cp.async.cg.shared.global [%0], [%1], 16;"
                 :: "r"(dst), "l"(src) : "memory");
}
__device__ __forceinline__ void cp_commit() {
    asm volatile("cp.async.commit_group;" ::: "memory");
}
template <int N> __device__ __forceinline__ void cp_wait() {
    asm volatile("cp.async.wait_group %0;" :: "n"(N) : "memory");
}
__device__ __forceinline__ void ldsm_x4(uint32_t& r0, uint32_t& r1,
                                        uint32_t& r2, uint32_t& r3, uint32_t a) {
    asm volatile("ldmatrix.sync.aligned.m8n8.x4.shared.b16 {%0,%1,%2,%3}, [%4];"
                 : "=r"(r0), "=r"(r1), "=r"(r2), "=r"(r3) : "r"(a));
}
__device__ __forceinline__ void mma_f16(float* c, const uint32_t* a,
                                        const uint32_t* b) {
    asm volatile(
        "mma.sync.aligned.m16n8k16.row.col.f32.f16.f16.f32 "
        "{%0,%1,%2,%3}, {%4,%5,%6,%7}, {%8,%9}, {%0,%1,%2,%3};"
        : "+f"(c[0]), "+f"(c[1]), "+f"(c[2]), "+f"(c[3])
        : "r"(a[0]), "r"(a[1]), "r"(a[2]), "r"(a[3]), "r"(b[0]), "r"(b[1]));
}

// -------- ids dtype detection (JAX x64-off downcasts int64 -> int32) --------
__device__ __forceinline__ bool ids_look_i64(const void* idsptr, int K) {
    const int* p = (const int*)idsptr;
    bool odd_zero = true, even_valid = true;
    for (int k = 1; k < K; k += 2) if (p[k] != 0) odd_zero = false;
    for (int k = 0; k < K; k += 2) if (p[k] < 0 || p[k] >= N_ADAPT) even_valid = false;
    return odd_zero && even_valid;
}
__device__ __forceinline__ int load_id(const void* idsptr, int k, bool is64) {
    return is64 ? (int)((const long long*)idsptr)[k] : ((const int*)idsptr)[k];
}

// ---------------------------------------------------------------------------
// Fused prep: blocks [0,4096): x->fp16 ; [4096,5120): Wmix->fp16 ; 5120: bias
// ---------------------------------------------------------------------------
#define XBLKS 4096
#define WBLKS 1024
__global__ void prep_all_kernel(const float* __restrict__ x,
                                const float* __restrict__ W,
                                const float* __restrict__ b,
                                const void* __restrict__ ids,
                                const float* __restrict__ wts, int K) {
    const int bid = blockIdx.x;
    if (bid < XBLKS) {
        const int i = bid * 256 + threadIdx.x;   // float4 index into x
        float4 v = __ldg(&((const float4*)x)[i]);
        __half2 p0 = make_half2(__float2half_rn(v.x), __float2half_rn(v.y));
        __half2 p1 = make_half2(__float2half_rn(v.z), __float2half_rn(v.w));
        ((__half2*)g_Xf)[i * 2]     = p0;
        ((__half2*)g_Xf)[i * 2 + 1] = p1;
    } else if (bid < XBLKS + WBLKS) {
        const bool is64 = ids_look_i64(ids, K);
        const int i = (bid - XBLKS) * 256 + threadIdx.x;  // float4 index into Wmix
        const int OD4 = D_OUT * D_IN / 4;
        const float4* W4 = (const float4*)W;
        float4 acc = make_float4(0.f, 0.f, 0.f, 0.f);
        for (int k = 0; k < K; k++) {
            float w = __ldg(&wts[k]);
            long long id = load_id(ids, k, is64);
            float4 v = __ldg(&W4[id * (long long)OD4 + i]);
            acc.x += w * v.x; acc.y += w * v.y; acc.z += w * v.z; acc.w += w * v.w;
        }
        __half2 p0 = make_half2(__float2half_rn(acc.x), __float2half_rn(acc.y));
        __half2 p1 = make_half2(__float2half_rn(acc.z), __float2half_rn(acc.w));
        ((__half2*)g_Wf)[i * 2]     = p0;
        ((__half2*)g_Wf)[i * 2 + 1] = p1;
    } else {
        const bool is64 = ids_look_i64(ids, K);
        for (int i = threadIdx.x; i < D_OUT; i += 256) {
            float acc = 0.f;
            for (int k = 0; k < K; k++) {
                long long id = load_id(ids, k, is64);
                acc += __ldg(&wts[k]) * __ldg(&b[id * (long long)D_OUT + i]);
            }
            g_bmix[i] = acc;
        }
    }
}

// ---------------------------------------------------------------------------
// GEMM: C[m,n] = sum_d x[m,d] Wmix[n,d] + bmix[n]
// CTA tile 128x128, K-chunk 64, 8 warps (2 in M x 4 in N), warp tile 64x32.
// 3-stage cp.async pipeline, one __syncthreads per chunk (16 chunks).
// Single fp16 pass, fp32 accumulate.
// ---------------------------------------------------------------------------
#define MTILE 128
#define NTILE 128
#define KC    64
#define NCH   (D_IN / KC)           // 16
#define RSTR  72                    // padded row stride (halves): 144B rows
#define XOFF  0
#define WOFF  (128 * RSTR)
#define STAGE_ELEMS (2 * 128 * RSTR)    // 18432 halves = 36864 B
#define NSTAGE 3
#define SMEM_BYTES (NSTAGE * STAGE_ELEMS * 2)   // 110592 B

__global__ void __launch_bounds__(256, 2)
gemm_mma_kernel(float* __restrict__ C) {
    extern __shared__ __half sm[];
    const uint32_t sbase = smem_u32(sm);

    const int tid    = threadIdx.x;
    const int lane   = tid & 31;
    const int wid    = tid >> 5;
    const int warp_m = wid & 1;
    const int warp_n = wid >> 1;
    const int m0 = blockIdx.y * MTILE;
    const int n0 = blockIdx.x * NTILE;

    // global->smem: row = tid>>1 (0..127); 4 x 16B chunks per thread per array.
    const int lrow = tid >> 1;
    const int lkh  = (tid & 1) * 32;          // half-offset: 0 or 32
    const __half* gX = g_Xf + (size_t)(m0 + lrow) * D_IN + lkh;
    const __half* gW = g_Wf + (size_t)(n0 + lrow) * D_IN + lkh;
    const uint32_t dst = (uint32_t)(lrow * RSTR + lkh) * 2;   // stage byte off

    auto load_stage = [&](int c) {
        const uint32_t sb = sbase + (uint32_t)(c % NSTAGE) * STAGE_ELEMS * 2;
        const size_t go = (size_t)c * KC;
#pragma unroll
        for (int j = 0; j < 4; j++) {
            const uint32_t d = dst + j * 16;
            cp_async16(sb + XOFF * 2 + d, gX + go + j * 8);
            cp_async16(sb + WOFF * 2 + d, gW + go + j * 8);
        }
    };

    // ldmatrix lane mapping (validated layout from R4/R5)
    const int a_row = (lane & 15);
    const int a_kof = (lane >> 4) * 8;
    const int b_row = ((lane >> 4) << 3) + (lane & 7);
    const int b_kof = ((lane >> 3) & 1) * 8;

    float acc[4][4][4];
#pragma unroll
    for (int i = 0; i < 4; i++)
#pragma unroll
        for (int j = 0; j < 4; j++)
#pragma unroll
            for (int q = 0; q < 4; q++) acc[i][j][q] = 0.f;

    load_stage(0); cp_commit();
    load_stage(1); cp_commit();

    for (int c = 0; c < NCH; c++) {
        cp_wait<NSTAGE - 2>();      // stage c resident
        __syncthreads();

        const uint32_t sb = sbase + (uint32_t)(c % NSTAGE) * STAGE_ELEMS * 2;
#pragma unroll
        for (int ks = 0; ks < KC / 16; ks++) {
            const int k0 = ks * 16;
            uint32_t af[4][4];
#pragma unroll
            for (int mf = 0; mf < 4; mf++) {
                const uint32_t ro =
                    (uint32_t)((warp_m * 64 + mf * 16 + a_row) * RSTR + k0 + a_kof) * 2;
                ldsm_x4(af[mf][0], af[mf][1], af[mf][2], af[mf][3], sb + XOFF * 2 + ro);
            }
            uint32_t bf[4][2];
#pragma unroll
            for (int ng = 0; ng < 2; ng++) {
                const uint32_t ro =
                    (uint32_t)((warp_n * 32 + ng * 16 + b_row) * RSTR + k0 + b_kof) * 2;
                uint32_t r0, r1, r2, r3;
                ldsm_x4(r0, r1, r2, r3, sb + WOFF * 2 + ro);
                bf[ng * 2][0] = r0; bf[ng * 2][1] = r1;
                bf[ng * 2 + 1][0] = r2; bf[ng * 2 + 1][1] = r3;
            }
#pragma unroll
            for (int mf = 0; mf < 4; mf++)
#pragma unroll
                for (int nf = 0; nf < 4; nf++)
                    mma_f16(acc[mf][nf], af[mf], bf[nf]);
        }

        if (c + NSTAGE - 1 < NCH) load_stage(c + NSTAGE - 1);
        cp_commit();    // unconditional: empty tail groups keep wait<> sound
    }

    // epilogue: add bias, store float2 pairs
    const int g = lane >> 2;
    const int cpair = (lane & 3) * 2;
#pragma unroll
    for (int mf = 0; mf < 4; mf++) {
        const int row = m0 + warp_m * 64 + mf * 16 + g;
#pragma unroll
        for (int nf = 0; nf < 4; nf++) {
            const int col = n0 + warp_n * 32 + nf * 8 + cpair;
            const float b0 = __ldg(&g_bmix[col]);
            const float b1 = __ldg(&g_bmix[col + 1]);
            float2 v0 = make_float2(acc[mf][nf][0] + b0, acc[mf][nf][1] + b1);
            float2 v1 = make_float2(acc[mf][nf][2] + b0, acc[mf][nf][3] + b1);
            *(float2*)(C + (size_t)row * D_OUT + col) = v0;
            *(float2*)(C + (size_t)(row + 8) * D_OUT + col) = v1;
        }
    }
}

// ---------------------------------------------------------------------------
extern "C" void kernel_launch(void* const* d_in, const int* in_sizes, int n_in,
                              void* d_out, int out_size) {
    const float* x   = (const float*)d_in[0];
    const float* W   = (const float*)d_in[1];
    const float* b   = (const float*)d_in[2];
    const void*  ids = d_in[3];
    const float* wts = (const float*)d_in[4];
    const int K = in_sizes[3];

    cudaFuncSetAttribute(gemm_mma_kernel,
                         cudaFuncAttributeMaxDynamicSharedMemorySize, SMEM_BYTES);

    prep_all_kernel<<<XBLKS + WBLKS + 1, 256>>>(x, W, b, ids, wts, K);

    dim3 grid(D_OUT / NTILE, M_TOTAL / MTILE);  // (8, 32) = 256 CTAs
    gemm_mma_kernel<<<grid, 256, SMEM_BYTES>>>((float*)d_out);
}